// round 12
// baseline (speedup 1.0000x reference)
#include <cuda_runtime.h>
#include <math.h>

#define B 128
#define T 1024
#define H 256
#define G4 1024   // 4*H

// ------------------- device scratch (static) -------------------
__device__ float    g_xp[(size_t)2 * T * B * G4];    // x@Wih.T + b, rows reordered (4*h+gate)
__device__ float    g_hstore[(size_t)2 * T * B * H]; // recorded h (fp32), [d][t][b][h]
__device__ unsigned g_WB[2 * 8 * 16 * 32 * 64];      // Whh as tf32 B-frag regs: [d][gx][w][lane][64]
__device__ float    g_outWT[512 * 32];               // out_W transposed: [k][j]
__device__ float    g_af[B * 32];                    // addr_feat
__device__ float    g_scores[B * T];

__device__ __forceinline__ float tanh_fast(float x) {
    float r;
    asm("tanh.approx.f32 %0, %1;" : "=f"(r) : "f"(x));
    return r;
}
__device__ __forceinline__ float sigm(float x) {
    return fmaf(0.5f, tanh_fast(0.5f * x), 0.5f);
}
__device__ __forceinline__ void mma_tf32(float c[4], uint4 a, unsigned b0, unsigned b1) {
    asm volatile("mma.sync.aligned.m16n8k8.row.col.f32.tf32.tf32.f32 "
                 "{%0,%1,%2,%3}, {%4,%5,%6,%7}, {%8,%9}, {%0,%1,%2,%3};"
                 : "+f"(c[0]), "+f"(c[1]), "+f"(c[2]), "+f"(c[3])
                 : "r"(a.x), "r"(a.y), "r"(a.z), "r"(a.w), "r"(b0), "r"(b1));
}
__device__ __forceinline__ unsigned to_tf32(float v) {
    unsigned u;
    asm("cvt.rna.tf32.f32 %0, %1;" : "=r"(u) : "f"(v));
    return u;
}

// smem layout (bytes): two h A-frag buffers + mbarriers
#define HT_BYTES 16384     // 32 ks x 32 lane x 4 u32
#define OFF_HT0  0
#define OFF_HT1  16384
#define OFF_MBAR 32768
#define LSTM_SMEM (124 * 1024)   // padded so each CTA owns an SM

// ------------------- weight prep: W as per-thread tf32 B-operand registers -------------------
// g_WB[((d*8+gx)*16+w)*2048 + lane*64 + j], j=2*ks+p:
//   p=0 -> W[rp][ks*8 + t],  p=1 -> W[rp][ks*8 + t + 4],  rp = gx*128 + w*8 + g
__global__ void prep_kernel(const float* __restrict__ Whh_f,
                            const float* __restrict__ Whh_b,
                            const float* __restrict__ out_W) {
    int idx = blockIdx.x * 256 + threadIdx.x;
    if (idx < 2 * 8 * 16 * 32 * 64) {
        int j    = idx & 63;
        int lane = (idx >> 6) & 31;
        int w    = (idx >> 11) & 15;
        int gxp  = (idx >> 15) & 7;
        int d    = idx >> 18;
        int g = lane >> 2, t = lane & 3;
        int ks = j >> 1, p = j & 1;
        int rp = gxp * 128 + w * 8 + g;      // reordered row r' = 4*jh + gate
        int gate = rp & 3, jh = rp >> 2;
        int k = ks * 8 + t + p * 4;
        const float* Whh = d ? Whh_b : Whh_f;
        g_WB[idx] = to_tf32(Whh[(gate * 256 + jh) * H + k]);
    }
    if (idx < 512 * 32) {
        int k = idx >> 5, j = idx & 31;
        g_outWT[idx] = out_W[j * 512 + k];
    }
}

// ------------------- addr_feat -------------------
__global__ void addr_kernel(const float* __restrict__ addr,
                            const int*   __restrict__ addr_type,
                            const float* __restrict__ poi_emb,
                            const float* __restrict__ addr_W,
                            const float* __restrict__ addr_b) {
    int b = threadIdx.x;  // 128
    float inp[4];
    inp[0] = addr[b];
    int at = addr_type[b];
    inp[1] = poi_emb[at * 3 + 0];
    inp[2] = poi_emb[at * 3 + 1];
    inp[3] = poi_emb[at * 3 + 2];
    for (int j = 0; j < 32; j++) {
        float a = addr_b[j];
        #pragma unroll
        for (int f = 0; f < 4; f++) a += addr_W[j * 4 + f] * inp[f];
        g_af[b * 32 + j] = a;
    }
}

// ------------------- xp = loc_seq @ Wih.T + b (reordered rows), active (b,t) only -------------------
__global__ void __launch_bounds__(256) xp_kernel(
    const float* __restrict__ loc_dense, const float* __restrict__ time_dist,
    const int* __restrict__ len, const float* __restrict__ time_W,
    const float* __restrict__ time_b,
    const float* __restrict__ Wih_f, const float* __restrict__ b_f,
    const float* __restrict__ Wih_b, const float* __restrict__ b_b) {
    int b = blockIdx.y, d = blockIdx.z;
    int t0 = blockIdx.x * 32;
    int n = len[b];
    if (t0 >= n) return;
    const float* Wih  = d ? Wih_b : Wih_f;
    const float* bias = d ? b_b  : b_f;

    __shared__ float loc19[32][19];
    int tid = threadIdx.x;
    for (int i = tid; i < 32 * 16; i += 256) {
        int tt = i >> 4, f = i & 15;
        loc19[tt][f] = loc_dense[((size_t)b * T + t0 + tt) * 16 + f];
    }
    if (tid < 96) {
        int tt = tid / 3, e = tid % 3;
        float acc = time_b[e];
        const float* tdp = &time_dist[((size_t)b * T + t0 + tt) * 8];
        #pragma unroll
        for (int f = 0; f < 8; f++) acc += time_W[e * 8 + f] * tdp[f];
        loc19[tt][16 + e] = acc;
    }
    __syncthreads();

    int j = tid;  // h index 0..255; owns reordered rows 4j..4j+3
    float w[4][19], bz[4];
    #pragma unroll
    for (int g = 0; g < 4; g++) {
        int orig = g * 256 + j;
        bz[g] = bias[orig];
        #pragma unroll
        for (int f = 0; f < 19; f++) w[g][f] = Wih[orig * 19 + f];
    }
    int tmax = min(32, n - t0);
    for (int tt = 0; tt < tmax; tt++) {
        float accs[4];
        #pragma unroll
        for (int g = 0; g < 4; g++) {
            float a = bz[g];
            #pragma unroll
            for (int f = 0; f < 19; f++) a += w[g][f] * loc19[tt][f];
            accs[g] = a;
        }
        float4 out4 = make_float4(accs[0], accs[1], accs[2], accs[3]);
        *(float4*)&g_xp[(((size_t)d * T + t0 + tt) * B + b) * G4 + j * 4] = out4;
    }
}

// ------------------- persistent bidirectional LSTM: transposed tf32 MMA, W in registers -------------------
// Grid (8,8,2), cluster (8,1,1) = 8 gate-tile CTAs sharing (btile, dir).
// gatesT[16 batch][128 rows] = hT[16][256] x WT[256][128]; W = B-operand in registers (64 u32/thread).
// h = A-operand, stored in MMA A-fragment layout in smem: hA[ks(32)][lane(32)][4] tf32.
// Warp w owns gate rows w*8..w*8+7 (= 2 LSTM cells x 16 batches = 32 threads).
// Epilogue: 2-shuffle gate gather, cell update in regs, DSMEM broadcast (8 u32 stores),
// per-warp release-arrive on double-buffered mbarriers (count 128). No block syncs in loop.
__global__ void __launch_bounds__(512, 1) __cluster_dims__(8, 1, 1)
lstm_kernel(const int* __restrict__ len) {
    extern __shared__ __align__(16) unsigned char smem[];

    int gx  = blockIdx.x;   // gate tile == cluster rank
    int gy  = blockIdx.y;
    int dir = blockIdx.z;
    int tid = threadIdx.x;
    int b0  = gy * 16;
    int nloc = len[b0];     // sorted descending -> tile max (same for whole cluster)

    int lane = tid & 31, wid = tid >> 5;
    int g = lane >> 2, t = lane & 3;

    unsigned mbar_local;
    asm("{ .reg .u64 tt; cvta.to.shared.u64 tt, %1; cvt.u32.u64 %0, tt; }"
        : "=r"(mbar_local) : "l"((void*)(smem + OFF_MBAR)));

    // W into registers: 64 u32 per thread (step-invariant)
    unsigned wreg[64];
    {
        const uint4* wsrc = reinterpret_cast<const uint4*>(g_WB) +
                            (size_t)((((dir * 8 + gx) * 16 + wid) * 32 + lane)) * 16;
        #pragma unroll
        for (int q = 0; q < 16; q++) {
            uint4 v = wsrc[q];
            wreg[4 * q + 0] = v.x; wreg[4 * q + 1] = v.y;
            wreg[4 * q + 2] = v.z; wreg[4 * q + 3] = v.w;
        }
    }
    for (int e = tid; e < HT_BYTES / 4; e += 512) ((unsigned*)(smem + OFF_HT0))[e] = 0u;
    if (tid == 0) {
        asm volatile("mbarrier.init.shared.b64 [%0], %1;" :: "r"(mbar_local), "r"(128) : "memory");
        asm volatile("mbarrier.init.shared.b64 [%0], %1;" :: "r"(mbar_local + 8), "r"(128) : "memory");
    }
    __syncthreads();

    // cell ownership: cell hl = wid*2 + (t>>1), batch bl = g + 8*(t&1)
    int hl  = wid * 2 + (t >> 1);
    int kme = gx * 32 + hl;          // h index within 256
    int bl  = g + 8 * (t & 1);
    int bme = b0 + bl;
    int mylen = len[bme];
    float c_reg = 0.0f, h_reg = 0.0f;

    // DSMEM slot of h[bl][kme] in the A-fragment layout
    unsigned rem[8];
    {
        int ksq = kme >> 3, r = kme & 7;
        int tt2 = r & 3, p = r >> 2;
        int lane_t = (bl & 7) * 4 + tt2;
        int slot = (p << 1) | (bl >> 3);
        unsigned* dst = (unsigned*)(smem + OFF_HT0) + (ksq * 32 + lane_t) * 4 + slot;
        unsigned lcl;
        asm("{ .reg .u64 tt; cvta.to.shared.u64 tt, %1; cvt.u32.u64 %0, tt; }"
            : "=r"(lcl) : "l"((void*)dst));
        #pragma unroll
        for (int r2 = 0; r2 < 8; r2++)
            asm("mapa.shared::cluster.u32 %0, %1, %2;" : "=r"(rem[r2]) : "r"(lcl), "r"(r2));
    }
    unsigned mbar_peer[8];
    #pragma unroll
    for (int r2 = 0; r2 < 8; r2++)
        asm("mapa.shared::cluster.u32 %0, %1, %2;" : "=r"(mbar_peer[r2]) : "r"(mbar_local), "r"(r2));

    // cluster-wide: smem + mbarriers initialized before any DSMEM traffic
    asm volatile("barrier.cluster.arrive.aligned;" ::: "memory");
    asm volatile("barrier.cluster.wait.aligned;"   ::: "memory");

    for (int i = 0; i < nloc; i++) {
        int cur = i & 1;
        const uint4* ha = reinterpret_cast<const uint4*>(smem + (cur ? OFF_HT1 : OFF_HT0)) + lane;
        int s = dir ? (nloc - 1 - i) : i;

        // xp prefetch: 4 gates of own cell (independent of h) BEFORE the wait
        float4 xp4 = *(const float4*)&g_xp[(((size_t)dir * T + s) * B + bme) * G4 +
                                           gx * 128 + wid * 8 + (t >> 1) * 4];

        // wait for step-i h buffer (all 128 warps of the cluster arrived)
        if (i > 0) {
            unsigned mb = mbar_local + (unsigned)(cur * 8);
            unsigned parity = ((i - 1) >> 1) & 1;
            unsigned done;
            do {
                asm volatile(
                    "{\n\t.reg .pred p;\n\t"
                    "mbarrier.try_wait.parity.acquire.cluster.shared::cta.b64 p, [%1], %2, 0x989680;\n\t"
                    "selp.b32 %0, 1, 0, p;\n\t}"
                    : "=r"(done) : "r"(mb), "r"(parity) : "memory");
            } while (!done);
        }

        // GEMM: 32 k-steps m16n8k8 tf32, A = h frags (LDS.128), B = W regs, 2 acc chains
        float c0[4] = {0.f, 0.f, 0.f, 0.f}, c1[4] = {0.f, 0.f, 0.f, 0.f};
        #pragma unroll
        for (int ks = 0; ks < 32; ks += 2) {
            uint4 a0 = ha[ks * 32];
            mma_tf32(c0, a0, wreg[2 * ks], wreg[2 * ks + 1]);
            uint4 a1 = ha[(ks + 1) * 32];
            mma_tf32(c1, a1, wreg[2 * ks + 2], wreg[2 * ks + 3]);
        }
        float d0 = c0[0] + c1[0];
        float d1 = c0[1] + c1[1];
        float d2 = c0[2] + c1[2];
        float d3 = c0[3] + c1[3];

        // gate gather: bfly xor 1 (partner t^1, same g)
        int sel = t & 1;
        float s0 = sel ? d0 : d2;
        float s1 = sel ? d1 : d3;
        float r0 = __shfl_xor_sync(0xffffffffu, s0, 1);
        float r1 = __shfl_xor_sync(0xffffffffu, s1, 1);
        float gi = (sel ? r0 : d0) + xp4.x;
        float gf = (sel ? r1 : d1) + xp4.y;
        float gg = (sel ? d2 : r0) + xp4.z;
        float go = (sel ? d3 : r1) + xp4.w;

        // cell update (c,h in regs)
        if (s < mylen) {
            float cn = sigm(gf) * c_reg + sigm(gi) * tanh_fast(gg);
            c_reg = cn;
            h_reg = sigm(go) * tanh_fast(cn);
            g_hstore[(((size_t)dir * T + s) * B + bme) * H + kme] = h_reg;
        }
        // DSMEM broadcast of tf32 h into all 8 ranks' next buffer
        {
            unsigned hv = to_tf32(h_reg);
            unsigned boff = cur ? 0u : (unsigned)HT_BYTES;
            #pragma unroll
            for (int r2 = 0; r2 < 8; r2++) {
                asm volatile("st.shared::cluster.b32 [%0], %1;"
                             :: "r"(rem[r2] + boff), "r"(hv) : "memory");
            }
        }
        __syncwarp();
        if (lane == 0) {
            unsigned off = ((i + 1) & 1) * 8;
            #pragma unroll
            for (int r2 = 0; r2 < 8; r2++) {
                asm volatile("mbarrier.arrive.release.cluster.shared::cluster.b64 _, [%0];"
                             :: "r"(mbar_peer[r2] + off) : "memory");
            }
        }
    }

    // DSMEM lifetime: no CTA exits while peers may still touch its smem
    asm volatile("barrier.cluster.arrive.aligned;" ::: "memory");
    asm volatile("barrier.cluster.wait.aligned;"   ::: "memory");
}

// ------------------- scores: comb_W . tanh(out_W @ [hf;hb] + addr_feat) -------------------
__global__ void __launch_bounds__(256) score_kernel(const int* __restrict__ len,
                                                    const float* __restrict__ comb_W) {
    int b = blockIdx.y;
    int t0 = blockIdx.x * 8;
    int n = len[b];
    if (t0 >= n) return;
    int w = threadIdx.x >> 5, lane = threadIdx.x & 31;
    int t = t0 + w;
    if (t >= n) return;
    float a0 = g_af[b * 32 + lane], a1 = 0.f, a2 = 0.f, a3 = 0.f;
    const float* hf = &g_hstore[(((size_t)0 * T + t) * B + b) * H];
    const float* hb = &g_hstore[(((size_t)1 * T + t) * B + b) * H];
    #pragma unroll 8
    for (int k = 0; k < 256; k += 4) {
        float4 h4 = *(const float4*)&hf[k];
        a0 = fmaf(g_outWT[(k + 0) * 32 + lane], h4.x, a0);
        a1 = fmaf(g_outWT[(k + 1) * 32 + lane], h4.y, a1);
        a2 = fmaf(g_outWT[(k + 2) * 32 + lane], h4.z, a2);
        a3 = fmaf(g_outWT[(k + 3) * 32 + lane], h4.w, a3);
    }
    #pragma unroll 8
    for (int k = 0; k < 256; k += 4) {
        float4 h4 = *(const float4*)&hb[k];
        a0 = fmaf(g_outWT[(256 + k + 0) * 32 + lane], h4.x, a0);
        a1 = fmaf(g_outWT[(256 + k + 1) * 32 + lane], h4.y, a1);
        a2 = fmaf(g_outWT[(256 + k + 2) * 32 + lane], h4.z, a2);
        a3 = fmaf(g_outWT[(256 + k + 3) * 32 + lane], h4.w, a3);
    }
    float v = tanhf(a0 + a1 + a2 + a3) * comb_W[lane];
    #pragma unroll
    for (int off = 16; off; off >>= 1) v += __shfl_down_sync(0xffffffffu, v, off);
    if (lane == 0) g_scores[b * T + t] = v;
}

// ------------------- masked log-softmax over T -------------------
__global__ void __launch_bounds__(256) softmax_kernel(const int* __restrict__ len,
                                                      float* __restrict__ out) {
    int b = blockIdx.x;
    int n = len[b];
    int tid = threadIdx.x;
    __shared__ float red[256];
    float m = -1e30f;
    for (int t = tid; t < n; t += 256) m = fmaxf(m, g_scores[b * T + t]);
    red[tid] = m; __syncthreads();
    for (int st = 128; st; st >>= 1) {
        if (tid < st) red[tid] = fmaxf(red[tid], red[tid + st]);
        __syncthreads();
    }
    m = red[0]; __syncthreads();
    float sum = 0.f;
    for (int t = tid; t < n; t += 256) sum += expf(g_scores[b * T + t] - m);
    red[tid] = sum; __syncthreads();
    for (int st = 128; st; st >>= 1) {
        if (tid < st) red[tid] += red[tid + st];
        __syncthreads();
    }
    float lse = m + logf(red[0]);
    for (int t = tid; t < T; t += 256)
        out[b * T + t] = (t < n) ? (g_scores[b * T + t] - lse) : 0.0f;
}

// ------------------- launch -------------------
extern "C" void kernel_launch(void* const* d_in, const int* in_sizes, int n_in,
                              void* d_out, int out_size) {
    (void)in_sizes; (void)n_in; (void)out_size;
    const float* addr      = (const float*)d_in[0];
    const int*   addr_type = (const int*)  d_in[1];
    const float* loc_dense = (const float*)d_in[2];
    const float* time_dist = (const float*)d_in[3];
    const int*   len       = (const int*)  d_in[4];
    const float* poi_emb   = (const float*)d_in[5];
    const float* time_W    = (const float*)d_in[6];
    const float* time_b    = (const float*)d_in[7];
    const float* addr_W    = (const float*)d_in[8];
    const float* addr_b    = (const float*)d_in[9];
    const float* Wih_f     = (const float*)d_in[10];
    const float* Whh_f     = (const float*)d_in[11];
    const float* b_f       = (const float*)d_in[12];
    const float* Wih_b     = (const float*)d_in[13];
    const float* Whh_b     = (const float*)d_in[14];
    const float* b_b       = (const float*)d_in[15];
    const float* out_W     = (const float*)d_in[16];
    const float* comb_W    = (const float*)d_in[17];
    float* out = (float*)d_out;

    static int smem_set = 0;
    if (!smem_set) {
        cudaFuncSetAttribute(lstm_kernel,
                             cudaFuncAttributeMaxDynamicSharedMemorySize, LSTM_SMEM);
        smem_set = 1;
    }

    addr_kernel<<<1, 128>>>(addr, addr_type, poi_emb, addr_W, addr_b);
    prep_kernel<<<8192, 256>>>(Whh_f, Whh_b, out_W);
    xp_kernel<<<dim3(32, 128, 2), 256>>>(loc_dense, time_dist, len, time_W, time_b,
                                         Wih_f, b_f, Wih_b, b_b);
    lstm_kernel<<<dim3(8, 8, 2), 512, LSTM_SMEM>>>(len);
    score_kernel<<<dim3(128, 128), 256>>>(len, comb_W);
    softmax_kernel<<<128, 256>>>(len, out);
}

// round 13
// speedup vs baseline: 1.6456x; 1.6456x over previous
#include <cuda_runtime.h>
#include <math.h>

#define B 128
#define T 1024
#define H 256
#define G4 1024   // 4*H
#define KS 36     // MMA k-steps: K = 288 = 256 h + 20 loc + 12 pad

// ------------------- device scratch (static) -------------------
__device__ float    g_loc[(size_t)T * B * 20];       // [t][b][20]: loc_dense(16) + td(3) + 1.0
__device__ float    g_hstore[(size_t)2 * T * B * H]; // recorded h (fp32), [d][t][b][h]
__device__ unsigned g_WB[2 * 8 * 8 * KS * 32 * 4];   // fused [Whh|Wih|b] tf32 A-frags
__device__ float    g_outWT[512 * 32];               // out_W transposed: [k][j]
__device__ float    g_af[B * 32];                    // addr_feat
__device__ float    g_scores[B * T];

__device__ __forceinline__ float tanh_fast(float x) {
    float r;
    asm("tanh.approx.f32 %0, %1;" : "=f"(r) : "f"(x));
    return r;
}
__device__ __forceinline__ float sigm(float x) {
    return fmaf(0.5f, tanh_fast(0.5f * x), 0.5f);
}
__device__ __forceinline__ void mma_tf32(float c[4], uint4 a, unsigned b0, unsigned b1) {
    asm volatile("mma.sync.aligned.m16n8k8.row.col.f32.tf32.tf32.f32 "
                 "{%0,%1,%2,%3}, {%4,%5,%6,%7}, {%8,%9}, {%0,%1,%2,%3};"
                 : "+f"(c[0]), "+f"(c[1]), "+f"(c[2]), "+f"(c[3])
                 : "r"(a.x), "r"(a.y), "r"(a.z), "r"(a.w), "r"(b0), "r"(b1));
}
__device__ __forceinline__ unsigned to_tf32(float v) {
    unsigned u;
    asm("cvt.rna.tf32.f32 %0, %1;" : "=r"(u) : "f"(v));
    return u;
}
// k-permuted position within a B row: (b0,b1) pairs adjacent for LDS.64
__device__ __forceinline__ int kpos(int k) {
    return (k & ~7) + 2 * (k & 3) + ((k >> 2) & 1);
}

// smem layout (bytes)
#define WF_BYTES  147456                 // 8 m x 36 ks x 32 lane x 4 u32
#define HROW      296                    // words per B row (296 % 32 == 8: conflict-free LDS.64)
#define HT_BYTES  (16 * HROW * 4)        // 18944
#define OFF_WF    0
#define OFF_HT0   WF_BYTES
#define OFF_HT1   (OFF_HT0 + HT_BYTES)
#define OFF_PRE   (OFF_HT1 + HT_BYTES)
#define OFF_MBAR  (OFF_PRE + 128 * 20 * 4)
#define LSTM_SMEM (OFF_MBAR + 16)

// ------------------- weight prep: fused tf32 A-fragments + outWT -------------------
__global__ void prep_kernel(const float* __restrict__ Whh_f, const float* __restrict__ Whh_b,
                            const float* __restrict__ Wih_f, const float* __restrict__ b_f,
                            const float* __restrict__ Wih_b, const float* __restrict__ b_b,
                            const float* __restrict__ out_W) {
    int idx = blockIdx.x * 256 + threadIdx.x;
    if (idx < 2 * 8 * 8 * KS * 32 * 4) {
        int r     = idx & 3;
        int lane  = (idx >> 2) & 31;
        int rest  = idx >> 7;
        int ks    = rest % KS;
        int rest2 = rest / KS;
        int m     = rest2 & 7;
        int gxp   = (rest2 >> 3) & 7;
        int d     = rest2 >> 6;
        int g = lane >> 2, t = lane & 3;
        int row_local = g + (r & 1) * 8;
        int k = ks * 8 + t + ((r & 2) ? 4 : 0);
        int rp = gxp * 128 + m * 16 + row_local;   // reordered row r' = 4*jh + gate
        int gate = rp & 3, jh = rp >> 2;
        int orig = gate * 256 + jh;
        float v;
        if (k < 256) {
            v = (d ? Whh_b : Whh_f)[orig * H + k];
        } else {
            int e = k - 256;
            if (e < 19)       v = (d ? Wih_b : Wih_f)[orig * 19 + e];
            else if (e == 19) v = (d ? b_b : b_f)[orig];
            else              v = 0.0f;
        }
        g_WB[idx] = to_tf32(v);
    }
    if (idx < 512 * 32) {
        int k = idx >> 5, j = idx & 31;
        g_outWT[idx] = out_W[j * 512 + k];
    }
}

// ------------------- addr_feat -------------------
__global__ void addr_kernel(const float* __restrict__ addr,
                            const int*   __restrict__ addr_type,
                            const float* __restrict__ poi_emb,
                            const float* __restrict__ addr_W,
                            const float* __restrict__ addr_b) {
    int b = threadIdx.x;  // 128
    float inp[4];
    inp[0] = addr[b];
    int at = addr_type[b];
    inp[1] = poi_emb[at * 3 + 0];
    inp[2] = poi_emb[at * 3 + 1];
    inp[3] = poi_emb[at * 3 + 2];
    for (int j = 0; j < 32; j++) {
        float a = addr_b[j];
        #pragma unroll
        for (int f = 0; f < 4; f++) a += addr_W[j * 4 + f] * inp[f];
        g_af[b * 32 + j] = a;
    }
}

// ------------------- loc_kernel: g_loc[t][b][20] = [loc_dense | td | 1], active only -------------------
__global__ void __launch_bounds__(320) loc_kernel(
    const float* __restrict__ loc_dense, const float* __restrict__ time_dist,
    const int* __restrict__ len, const float* __restrict__ time_W,
    const float* __restrict__ time_b) {
    int b = blockIdx.y;
    int t0 = blockIdx.x * 16;
    int n = len[b];
    if (t0 >= n) return;
    int tid = threadIdx.x;
    int tt = tid / 20, e = tid - tt * 20;
    int t = t0 + tt;
    if (t >= n) return;
    float v;
    if (e < 16) {
        v = loc_dense[((size_t)b * T + t) * 16 + e];
    } else if (e < 19) {
        int w = e - 16;
        float acc = time_b[w];
        const float* tdp = &time_dist[((size_t)b * T + t) * 8];
        #pragma unroll
        for (int f = 0; f < 8; f++) acc += time_W[w * 8 + f] * tdp[f];
        v = acc;
    } else {
        v = 1.0f;   // bias lane
    }
    g_loc[((size_t)t * B + b) * 20 + e] = v;
}

// ------------------- persistent bidirectional LSTM: fused-K tf32 MMA + mbarrier DSMEM sync ------------
// Grid (8,8,2), cluster (8,1,1) = 8 gate-tile CTAs sharing (btile, dir).
// gates[128 rows][16 b] = [Whh|Wih|b] (A, smem frags) x [h; loc; 1] (B, smem k-permuted rows).
// K = 288: k<256 = h (DSMEM-exchanged), k 256..275 = loc+bias input (staged locally per step).
// Sync identical to R10: 2 block syncs, count=8 double-buffered mbarriers, tids 0-7 arrive.
__global__ void __launch_bounds__(512, 1) __cluster_dims__(8, 1, 1)
lstm_kernel(const int* __restrict__ len) {
    extern __shared__ __align__(16) unsigned char smem[];
    float* pre = (float*)(smem + OFF_PRE);           // [128 rows][20 b]

    int gx  = blockIdx.x;   // gate tile == cluster rank
    int gy  = blockIdx.y;
    int dir = blockIdx.z;
    int tid = threadIdx.x;
    int b0  = gy * 16;
    int nloc = len[b0];     // sorted descending -> tile max (same for whole cluster)

    unsigned mbar_local;
    asm("{ .reg .u64 tt; cvta.to.shared.u64 tt, %1; cvt.u32.u64 %0, tt; }"
        : "=r"(mbar_local) : "l"((void*)(smem + OFF_MBAR)));

    // resident fused weight fragments (144 KB)
    {
        const uint4* Wf = reinterpret_cast<const uint4*>(g_WB) + (size_t)(dir * 8 + gx) * 9216;
        uint4* dst = reinterpret_cast<uint4*>(smem + OFF_WF);
        for (int e = tid; e < 9216; e += 512) dst[e] = Wf[e];
    }
    for (int e = tid; e < 2 * HT_BYTES / 4; e += 512) ((unsigned*)(smem + OFF_HT0))[e] = 0u;
    if (tid == 0) {
        asm volatile("mbarrier.init.shared.b64 [%0], %1;" :: "r"(mbar_local), "r"(8) : "memory");
        asm volatile("mbarrier.init.shared.b64 [%0], %1;" :: "r"(mbar_local + 8), "r"(8) : "memory");
    }
    __syncthreads();

    // loc staging ownership (tid < 320): element e of batch bl, smem position fixed
    int bl_st = tid / 20, e_st = tid - bl_st * 20;
    int pos_st = kpos(256 + e_st);
    bool stager = (tid < 320);

    // stage loc for step 0 into buffer 0
    {
        int s0 = dir ? (nloc - 1) : 0;
        if (stager) {
            float v = g_loc[((size_t)s0 * B + b0 + bl_st) * 20 + e_st];
            ((float*)(smem + OFF_HT0))[bl_st * HROW + pos_st] = v;
        }
    }

    int lane = tid & 31, wid = tid >> 5;
    int g = lane >> 2, t = lane & 3;
    int m = wid & 7, n = wid >> 3;

    // epilogue ownership: 1 cell per thread (hl 0..31, b2 0..15)
    int hl = tid & 31, b2 = tid >> 5;
    int bme = b0 + b2;
    int mylen = len[bme];
    float c_reg = 0.0f, h_reg = 0.0f;

    // remote DSMEM addrs of this thread's h slot (k-permuted, base in hT0) for all ranks
    unsigned rem[8];
    {
        int kme = gx * 32 + hl;
        unsigned char* dst = smem + OFF_HT0 + (b2 * HROW + kpos(kme)) * 4;
        unsigned lcl;
        asm("{ .reg .u64 tt; cvta.to.shared.u64 tt, %1; cvt.u32.u64 %0, tt; }"
            : "=r"(lcl) : "l"((void*)dst));
        #pragma unroll
        for (int r = 0; r < 8; r++)
            asm("mapa.shared::cluster.u32 %0, %1, %2;" : "=r"(rem[r]) : "r"(lcl), "r"(r));
    }
    unsigned mbar_peer[2] = {0u, 0u};
    if (tid < 8) {
        asm("mapa.shared::cluster.u32 %0, %1, %2;" : "=r"(mbar_peer[0]) : "r"(mbar_local), "r"(tid));
        mbar_peer[1] = mbar_peer[0] + 8;
    }

    // cluster-wide: smem + mbarriers initialized before any DSMEM traffic
    asm volatile("barrier.cluster.arrive.aligned;" ::: "memory");
    asm volatile("barrier.cluster.wait.aligned;"   ::: "memory");

    for (int i = 0; i < nloc; i++) {
        int cur = i & 1;
        const float* hCf = (const float*)(smem + (cur ? OFF_HT1 : OFF_HT0));
        float* hNf = (float*)(smem + (cur ? OFF_HT0 : OFF_HT1));
        int s = dir ? (nloc - 1 - i) : i;

        // prefetch next step's loc slice (independent of recurrence) BEFORE the wait
        float stage_val = 0.0f;
        bool do_stage = stager && (i + 1 < nloc);
        if (do_stage) {
            int s_next = dir ? (nloc - 2 - i) : (i + 1);
            stage_val = g_loc[((size_t)s_next * B + b0 + bl_st) * 20 + e_st];
        }

        // wait for step-i h buffer (peers' epilogue of step i-1)
        if (i > 0) {
            unsigned mb = mbar_local + (unsigned)(cur * 8);
            unsigned parity = ((i - 1) >> 1) & 1;
            unsigned done;
            do {
                asm volatile(
                    "{\n\t.reg .pred p;\n\t"
                    "mbarrier.try_wait.parity.acquire.cluster.shared::cta.b64 p, [%1], %2, 0x989680;\n\t"
                    "selp.b32 %0, 1, 0, p;\n\t}"
                    : "=r"(done) : "r"(mb), "r"(parity) : "memory");
            } while (!done);
        }

        // store staged loc into the NEXT buffer (its prior readers finished last step)
        if (do_stage) hNf[bl_st * HROW + pos_st] = stage_val;

        // GEMM: 36 k-steps m16n8k8 tf32; A = W frags (LDS.128), B = k-paired rows (LDS.64)
        float c0[4] = {0.f, 0.f, 0.f, 0.f}, c1[4] = {0.f, 0.f, 0.f, 0.f};
        {
            const uint4* ap = reinterpret_cast<const uint4*>(smem + OFF_WF) + m * (KS * 32) + lane;
            const uint2* hb2 = reinterpret_cast<const uint2*>(hCf + (n * 8 + g) * HROW) + t;
            #pragma unroll
            for (int ks = 0; ks < KS; ks += 2) {
                uint4 a0 = ap[ks * 32];
                uint2 bv0 = hb2[ks * 4];
                mma_tf32(c0, a0, bv0.x, bv0.y);
                uint4 a1 = ap[(ks + 1) * 32];
                uint2 bv1 = hb2[(ks + 1) * 4];
                mma_tf32(c1, a1, bv1.x, bv1.y);
            }
        }
        {
            int bl = n * 8 + 2 * t;
            *(float2*)&pre[(m * 16 + g) * 20 + bl]     = make_float2(c0[0] + c1[0], c0[1] + c1[1]);
            *(float2*)&pre[(m * 16 + g + 8) * 20 + bl] = make_float2(c0[2] + c1[2], c0[3] + c1[3]);
        }
        __syncthreads();

        // epilogue: 1 cell per thread; DSMEM broadcast of tf32 h
        if (s < mylen) {
            float gi = pre[(4 * hl + 0) * 20 + b2];
            float gf = pre[(4 * hl + 1) * 20 + b2];
            float gg = pre[(4 * hl + 2) * 20 + b2];
            float go = pre[(4 * hl + 3) * 20 + b2];
            float cn = sigm(gf) * c_reg + sigm(gi) * tanh_fast(gg);
            c_reg = cn;
            h_reg = sigm(go) * tanh_fast(cn);
            g_hstore[(((size_t)dir * T + s) * B + bme) * H + gx * 32 + hl] = h_reg;
        }
        {
            unsigned hv = to_tf32(h_reg);
            unsigned boff = cur ? 0u : (unsigned)HT_BYTES;   // target hN = other buffer
            #pragma unroll
            for (int r = 0; r < 8; r++) {
                asm volatile("st.shared::cluster.b32 [%0], %1;"
                             :: "r"(rem[r] + boff), "r"(hv) : "memory");
            }
        }
        __syncthreads();
        // signal buffer (i+1)&1 full: one release-arrive per peer from tids 0-7
        if (tid < 8) {
            unsigned mb = mbar_peer[(i + 1) & 1];
            asm volatile("mbarrier.arrive.release.cluster.shared::cluster.b64 _, [%0];"
                         :: "r"(mb) : "memory");
        }
    }

    // DSMEM lifetime: no CTA exits while peers may still touch its smem
    asm volatile("barrier.cluster.arrive.aligned;" ::: "memory");
    asm volatile("barrier.cluster.wait.aligned;"   ::: "memory");
}

// ------------------- scores: comb_W . tanh(out_W @ [hf;hb] + addr_feat) -------------------
__global__ void __launch_bounds__(256) score_kernel(const int* __restrict__ len,
                                                    const float* __restrict__ comb_W) {
    int b = blockIdx.y;
    int t0 = blockIdx.x * 8;
    int n = len[b];
    if (t0 >= n) return;
    int w = threadIdx.x >> 5, lane = threadIdx.x & 31;
    int t = t0 + w;
    if (t >= n) return;
    float a0 = g_af[b * 32 + lane], a1 = 0.f, a2 = 0.f, a3 = 0.f;
    const float* hf = &g_hstore[(((size_t)0 * T + t) * B + b) * H];
    const float* hb = &g_hstore[(((size_t)1 * T + t) * B + b) * H];
    #pragma unroll 8
    for (int k = 0; k < 256; k += 4) {
        float4 h4 = *(const float4*)&hf[k];
        a0 = fmaf(g_outWT[(k + 0) * 32 + lane], h4.x, a0);
        a1 = fmaf(g_outWT[(k + 1) * 32 + lane], h4.y, a1);
        a2 = fmaf(g_outWT[(k + 2) * 32 + lane], h4.z, a2);
        a3 = fmaf(g_outWT[(k + 3) * 32 + lane], h4.w, a3);
    }
    #pragma unroll 8
    for (int k = 0; k < 256; k += 4) {
        float4 h4 = *(const float4*)&hb[k];
        a0 = fmaf(g_outWT[(256 + k + 0) * 32 + lane], h4.x, a0);
        a1 = fmaf(g_outWT[(256 + k + 1) * 32 + lane], h4.y, a1);
        a2 = fmaf(g_outWT[(256 + k + 2) * 32 + lane], h4.z, a2);
        a3 = fmaf(g_outWT[(256 + k + 3) * 32 + lane], h4.w, a3);
    }
    float v = tanhf(a0 + a1 + a2 + a3) * comb_W[lane];
    #pragma unroll
    for (int off = 16; off; off >>= 1) v += __shfl_down_sync(0xffffffffu, v, off);
    if (lane == 0) g_scores[b * T + t] = v;
}

// ------------------- masked log-softmax over T -------------------
__global__ void __launch_bounds__(256) softmax_kernel(const int* __restrict__ len,
                                                      float* __restrict__ out) {
    int b = blockIdx.x;
    int n = len[b];
    int tid = threadIdx.x;
    __shared__ float red[256];
    float m = -1e30f;
    for (int t = tid; t < n; t += 256) m = fmaxf(m, g_scores[b * T + t]);
    red[tid] = m; __syncthreads();
    for (int st = 128; st; st >>= 1) {
        if (tid < st) red[tid] = fmaxf(red[tid], red[tid + st]);
        __syncthreads();
    }
    m = red[0]; __syncthreads();
    float sum = 0.f;
    for (int t = tid; t < n; t += 256) sum += expf(g_scores[b * T + t] - m);
    red[tid] = sum; __syncthreads();
    for (int st = 128; st; st >>= 1) {
        if (tid < st) red[tid] += red[tid + st];
        __syncthreads();
    }
    float lse = m + logf(red[0]);
    for (int t = tid; t < T; t += 256)
        out[b * T + t] = (t < n) ? (g_scores[b * T + t] - lse) : 0.0f;
}

// ------------------- launch -------------------
extern "C" void kernel_launch(void* const* d_in, const int* in_sizes, int n_in,
                              void* d_out, int out_size) {
    (void)in_sizes; (void)n_in; (void)out_size;
    const float* addr      = (const float*)d_in[0];
    const int*   addr_type = (const int*)  d_in[1];
    const float* loc_dense = (const float*)d_in[2];
    const float* time_dist = (const float*)d_in[3];
    const int*   len       = (const int*)  d_in[4];
    const float* poi_emb   = (const float*)d_in[5];
    const float* time_W    = (const float*)d_in[6];
    const float* time_b    = (const float*)d_in[7];
    const float* addr_W    = (const float*)d_in[8];
    const float* addr_b    = (const float*)d_in[9];
    const float* Wih_f     = (const float*)d_in[10];
    const float* Whh_f     = (const float*)d_in[11];
    const float* b_f       = (const float*)d_in[12];
    const float* Wih_b     = (const float*)d_in[13];
    const float* Whh_b     = (const float*)d_in[14];
    const float* b_b       = (const float*)d_in[15];
    const float* out_W     = (const float*)d_in[16];
    const float* comb_W    = (const float*)d_in[17];
    float* out = (float*)d_out;

    static int smem_set = 0;
    if (!smem_set) {
        cudaFuncSetAttribute(lstm_kernel,
                             cudaFuncAttributeMaxDynamicSharedMemorySize, LSTM_SMEM);
        smem_set = 1;
    }

    addr_kernel<<<1, 128>>>(addr, addr_type, poi_emb, addr_W, addr_b);
    prep_kernel<<<4608, 256>>>(Whh_f, Whh_b, Wih_f, b_f, Wih_b, b_b, out_W);
    loc_kernel<<<dim3(64, 128), 320>>>(loc_dense, time_dist, len, time_W, time_b);
    lstm_kernel<<<dim3(8, 8, 2), 512, LSTM_SMEM>>>(len);
    score_kernel<<<dim3(128, 128), 256>>>(len, comb_W);
    softmax_kernel<<<128, 256>>>(len, out);
}